// round 3
// baseline (speedup 1.0000x reference)
#include <cuda_runtime.h>
#include <cuda_bf16.h>

// ---------------------------------------------------------------------------
// MultiHeadAttentionBlock — softmax result is DISCARDED => attention is LINEAR:
//   (Q K^T / 8) V == Q (K^T V / 8).
// Pipeline (all GEMMs on tensor cores, bf16 hi/lo split = 3 MMAs, err ~1.5e-5):
//   0) split q,k,v, Wq,Wk,Wv to bf16 hi/lo (once)
//   1) Q = q Wq^T + bq (epilogue emits bf16 hi/lo) ; K,V same but fp32 out
//   2) M[b,h] = K_h^T V_h / 8   (split-S partials + deterministic reduce)
//   3) WcombT[b][c][h*64+i] = sum_j M[b,h][i,j] Wo[c,h*64+j]  (emit bf16 h/l)
//   4) out_b = Q_b @ WcombT_b^T + bo
// ---------------------------------------------------------------------------

#define Bsz 2
#define Ssz 2048
#define Dsz 1024
#define Hsz 16
#define DKsz 64
#define NCH 32   // S-chunks for ktv (chunk = 64 rows)

#define NELEM (Bsz * Ssz * Dsz)      // 4,194,304
#define WELEM (Dsz * Dsz)            // 1,048,576

// Scratch (no cudaMalloc allowed)
__device__ __nv_bfloat16 g_qh[NELEM], g_ql[NELEM];
__device__ __nv_bfloat16 g_kh[NELEM], g_kl[NELEM];
__device__ __nv_bfloat16 g_vh[NELEM], g_vl[NELEM];
__device__ __nv_bfloat16 g_wqh[WELEM], g_wql[WELEM];
__device__ __nv_bfloat16 g_wkh[WELEM], g_wkl[WELEM];
__device__ __nv_bfloat16 g_wvh[WELEM], g_wvl[WELEM];
__device__ __nv_bfloat16 g_Qh[NELEM], g_Ql[NELEM];
__device__ float g_K[NELEM];
__device__ float g_V[NELEM];
__device__ float g_Mpart[NCH * Bsz * Hsz * DKsz * DKsz];
__device__ float g_M[Bsz * Hsz * DKsz * DKsz];
__device__ __nv_bfloat16 g_WTh[Bsz * Dsz * Dsz], g_WTl[Bsz * Dsz * Dsz];

// ---------------------------------------------------------------------------
// PTX helpers
// ---------------------------------------------------------------------------
__device__ __forceinline__ void ldsm4(unsigned r[4], const __nv_bfloat16* p) {
    unsigned a = (unsigned)__cvta_generic_to_shared(p);
    asm volatile("ldmatrix.sync.aligned.m8n8.x4.shared.b16 {%0,%1,%2,%3}, [%4];\n"
                 : "=r"(r[0]), "=r"(r[1]), "=r"(r[2]), "=r"(r[3]) : "r"(a));
}

__device__ __forceinline__ void mma_bf16(float c[4], const unsigned a[4], const unsigned b[2]) {
    asm volatile("mma.sync.aligned.m16n8k16.row.col.f32.bf16.bf16.f32 "
                 "{%0,%1,%2,%3}, {%4,%5,%6,%7}, {%8,%9}, {%0,%1,%2,%3};\n"
                 : "+f"(c[0]), "+f"(c[1]), "+f"(c[2]), "+f"(c[3])
                 : "r"(a[0]), "r"(a[1]), "r"(a[2]), "r"(a[3]), "r"(b[0]), "r"(b[1]));
}

__device__ __forceinline__ void cpa16(__nv_bfloat16* dst, const __nv_bfloat16* src) {
    unsigned d = (unsigned)__cvta_generic_to_shared(dst);
    asm volatile("cp.async.cg.shared.global [%0], [%1], 16;\n" :: "r"(d), "l"(src));
}
__device__ __forceinline__ void cpa_commit() { asm volatile("cp.async.commit_group;\n"); }
__device__ __forceinline__ void cpa_wait0()  { asm volatile("cp.async.wait_group 0;\n"); }

// ---------------------------------------------------------------------------
// fp32 -> bf16 hi/lo split (vectorized)
// ---------------------------------------------------------------------------
__global__ __launch_bounds__(256)
void split_kernel(const float* __restrict__ x, __nv_bfloat16* __restrict__ xh,
                  __nv_bfloat16* __restrict__ xl, int n4)
{
    const int i = blockIdx.x * 256 + threadIdx.x;
    if (i >= n4) return;
    float4 v = ((const float4*)x)[i];
    __nv_bfloat16 h0 = __float2bfloat16_rn(v.x);
    __nv_bfloat16 h1 = __float2bfloat16_rn(v.y);
    __nv_bfloat16 h2 = __float2bfloat16_rn(v.z);
    __nv_bfloat16 h3 = __float2bfloat16_rn(v.w);
    __nv_bfloat16 l0 = __float2bfloat16_rn(v.x - __bfloat162float(h0));
    __nv_bfloat16 l1 = __float2bfloat16_rn(v.y - __bfloat162float(h1));
    __nv_bfloat16 l2 = __float2bfloat16_rn(v.z - __bfloat162float(h2));
    __nv_bfloat16 l3 = __float2bfloat16_rn(v.w - __bfloat162float(h3));
    ((__nv_bfloat162*)xh)[2 * i]     = __halves2bfloat162(h0, h1);
    ((__nv_bfloat162*)xh)[2 * i + 1] = __halves2bfloat162(h2, h3);
    ((__nv_bfloat162*)xl)[2 * i]     = __halves2bfloat162(l0, l1);
    ((__nv_bfloat162*)xl)[2 * i + 1] = __halves2bfloat162(l2, l3);
}

// ---------------------------------------------------------------------------
// Tensor-core GEMM (NT + bias, batched, bf16 hi/lo pre-split inputs):
//   C[z][M,N] = A[z][M,K] @ B[z][N,K]^T + bias[N]
// 128x128 tile, BK=32, 8 warps (2m x 4n), warp tile 64x32, cp.async 2-stage.
// Output: fp32 (Cf) or bf16 hi/lo pair (Ch,Cl).
// ---------------------------------------------------------------------------
#define STAGE_H (4 * 128 * 40)  // halves per stage (Ah,Al,Bh,Bl each 128x40)

__global__ __launch_bounds__(256)
void gemm_bf16(const __nv_bfloat16* __restrict__ Agh, const __nv_bfloat16* __restrict__ Agl,
               const __nv_bfloat16* __restrict__ Bgh, const __nv_bfloat16* __restrict__ Bgl,
               const float* __restrict__ bias,
               float* __restrict__ Cf, __nv_bfloat16* __restrict__ Ch, __nv_bfloat16* __restrict__ Cl,
               int M, int N, int K, long sA, long sB, long sC)
{
    extern __shared__ __align__(16) __nv_bfloat16 smem[];

    Agh += (long)blockIdx.z * sA; Agl += (long)blockIdx.z * sA;
    Bgh += (long)blockIdx.z * sB; Bgl += (long)blockIdx.z * sB;

    const int bm = blockIdx.y * 128, bn = blockIdx.x * 128;
    const int tid = threadIdx.x, lane = tid & 31, warp = tid >> 5;
    const int wm = warp >> 2, wn = warp & 3;

    // loader mapping: each thread 2 rows per tile, 16B chunk
    const int lrow = tid >> 2;          // 0..63
    const int lcol = (tid & 3) * 8;     // 0,8,16,24 (halves)

    float acc[4][4][4];
    #pragma unroll
    for (int mt = 0; mt < 4; mt++)
        #pragma unroll
        for (int nt = 0; nt < 4; nt++)
            #pragma unroll
            for (int e = 0; e < 4; e++) acc[mt][nt][e] = 0.f;

    // stage load
    auto load_stage = [&](int buf, int k0) {
        __nv_bfloat16* S = smem + buf * STAGE_H;
        __nv_bfloat16* sAh = S;
        __nv_bfloat16* sAl = S + 128 * 40;
        __nv_bfloat16* sBh = S + 2 * 128 * 40;
        __nv_bfloat16* sBl = S + 3 * 128 * 40;
        #pragma unroll
        for (int r = 0; r < 128; r += 64) {
            const long ga = (long)(bm + lrow + r) * K + k0 + lcol;
            const long gb = (long)(bn + lrow + r) * K + k0 + lcol;
            cpa16(sAh + (lrow + r) * 40 + lcol, Agh + ga);
            cpa16(sAl + (lrow + r) * 40 + lcol, Agl + ga);
            cpa16(sBh + (lrow + r) * 40 + lcol, Bgh + gb);
            cpa16(sBl + (lrow + r) * 40 + lcol, Bgl + gb);
        }
        cpa_commit();
    };

    load_stage(0, 0);

    int buf = 0;
    for (int k0 = 0; k0 < K; k0 += 32) {
        cpa_wait0();
        __syncthreads();
        if (k0 + 32 < K) load_stage(buf ^ 1, k0 + 32);

        const __nv_bfloat16* S = smem + buf * STAGE_H;
        const __nv_bfloat16* sAh = S;
        const __nv_bfloat16* sAl = S + 128 * 40;
        const __nv_bfloat16* sBh = S + 2 * 128 * 40;
        const __nv_bfloat16* sBl = S + 3 * 128 * 40;

        #pragma unroll
        for (int kk = 0; kk < 32; kk += 16) {
            unsigned aH[4][4], aL[4][4], bH[4][2], bL[4][2];
            const int arow = wm * 64 + (lane & 15);
            const int acol = kk + (lane >> 4) * 8;
            #pragma unroll
            for (int mt = 0; mt < 4; mt++) {
                ldsm4(aH[mt], sAh + (arow + mt * 16) * 40 + acol);
                ldsm4(aL[mt], sAl + (arow + mt * 16) * 40 + acol);
            }
            const int g = lane >> 3;
            #pragma unroll
            for (int p = 0; p < 2; p++) {
                const int brow = wn * 32 + p * 16 + ((g >> 1) << 3) + (lane & 7);
                const int bcol = kk + (g & 1) * 8;
                unsigned t[4];
                ldsm4(t, sBh + brow * 40 + bcol);
                bH[2 * p][0] = t[0]; bH[2 * p][1] = t[1];
                bH[2 * p + 1][0] = t[2]; bH[2 * p + 1][1] = t[3];
                ldsm4(t, sBl + brow * 40 + bcol);
                bL[2 * p][0] = t[0]; bL[2 * p][1] = t[1];
                bL[2 * p + 1][0] = t[2]; bL[2 * p + 1][1] = t[3];
            }
            #pragma unroll
            for (int mt = 0; mt < 4; mt++)
                #pragma unroll
                for (int nt = 0; nt < 4; nt++) {
                    mma_bf16(acc[mt][nt], aH[mt], bH[nt]);
                    mma_bf16(acc[mt][nt], aH[mt], bL[nt]);
                    mma_bf16(acc[mt][nt], aL[mt], bH[nt]);
                }
        }
        __syncthreads();
        buf ^= 1;
    }

    // Epilogue
    const int crow = bm + wm * 64 + lane / 4;
    const int ccol0 = bn + wn * 32 + (lane % 4) * 2;
    #pragma unroll
    for (int mt = 0; mt < 4; mt++) {
        #pragma unroll
        for (int nt = 0; nt < 4; nt++) {
            const int col = ccol0 + nt * 8;
            const float2 bb = *(const float2*)(bias + col);
            const int r0 = crow + mt * 16;
            float o00 = acc[mt][nt][0] + bb.x, o01 = acc[mt][nt][1] + bb.y;
            float o10 = acc[mt][nt][2] + bb.x, o11 = acc[mt][nt][3] + bb.y;
            if (Cf) {
                float* Cz = Cf + (long)blockIdx.z * sC;
                *(float2*)(Cz + (long)r0 * N + col) = make_float2(o00, o01);
                *(float2*)(Cz + (long)(r0 + 8) * N + col) = make_float2(o10, o11);
            } else {
                __nv_bfloat16 h00 = __float2bfloat16_rn(o00), h01 = __float2bfloat16_rn(o01);
                __nv_bfloat16 h10 = __float2bfloat16_rn(o10), h11 = __float2bfloat16_rn(o11);
                __nv_bfloat162 lo0 = __halves2bfloat162(
                    __float2bfloat16_rn(o00 - __bfloat162float(h00)),
                    __float2bfloat16_rn(o01 - __bfloat162float(h01)));
                __nv_bfloat162 lo1 = __halves2bfloat162(
                    __float2bfloat16_rn(o10 - __bfloat162float(h10)),
                    __float2bfloat16_rn(o11 - __bfloat162float(h11)));
                __nv_bfloat16* Chz = Ch + (long)blockIdx.z * sC;
                __nv_bfloat16* Clz = Cl + (long)blockIdx.z * sC;
                *(__nv_bfloat162*)(Chz + (long)r0 * N + col) = __halves2bfloat162(h00, h01);
                *(__nv_bfloat162*)(Chz + (long)(r0 + 8) * N + col) = __halves2bfloat162(h10, h11);
                *(__nv_bfloat162*)(Clz + (long)r0 * N + col) = lo0;
                *(__nv_bfloat162*)(Clz + (long)(r0 + 8) * N + col) = lo1;
            }
        }
    }
}

// ---------------------------------------------------------------------------
// Partial M: Mpart[chunk][b,h][i][j] = sum_{s in chunk} K[b,s,h*64+i]*V[b,s,h*64+j]
// ---------------------------------------------------------------------------
__global__ __launch_bounds__(256)
void ktv_kernel(const float* __restrict__ Kp, const float* __restrict__ Vp,
                float* __restrict__ Mpart)
{
    __shared__ float Ks[32][64];
    __shared__ float Vs[32][64];
    const int bh = blockIdx.x;
    const int b = bh >> 4;
    const int h = bh & 15;
    const int chunk = blockIdx.y;
    const int tid = threadIdx.x;
    const int ti = (tid >> 4) * 4;
    const int tj = (tid & 15) * 4;
    const size_t base = (size_t)b * Ssz * Dsz + h * DKsz;

    float acc[4][4] = {};
    const int s_begin = chunk * (Ssz / NCH);
    for (int s0 = s_begin; s0 < s_begin + Ssz / NCH; s0 += 32) {
        #pragma unroll
        for (int it = 0; it < 2; it++) {
            const int idx = tid + it * 256;
            const int srow = idx >> 4;
            const int scol = (idx & 15) << 2;
            *(float4*)&Ks[srow][scol] =
                *(const float4*)(Kp + base + (size_t)(s0 + srow) * Dsz + scol);
            *(float4*)&Vs[srow][scol] =
                *(const float4*)(Vp + base + (size_t)(s0 + srow) * Dsz + scol);
        }
        __syncthreads();
        #pragma unroll
        for (int ss = 0; ss < 32; ss++) {
            float4 ka = *(const float4*)&Ks[ss][ti];
            float4 vb = *(const float4*)&Vs[ss][tj];
            const float a[4] = {ka.x, ka.y, ka.z, ka.w};
            const float w[4] = {vb.x, vb.y, vb.z, vb.w};
            #pragma unroll
            for (int i = 0; i < 4; i++)
                #pragma unroll
                for (int j = 0; j < 4; j++) acc[i][j] += a[i] * w[j];
        }
        __syncthreads();
    }
    float* outp = Mpart + (long)chunk * (Bsz * Hsz * DKsz * DKsz) + (long)bh * (DKsz * DKsz);
    #pragma unroll
    for (int i = 0; i < 4; i++)
        *(float4*)(outp + (ti + i) * DKsz + tj) =
            make_float4(acc[i][0], acc[i][1], acc[i][2], acc[i][3]);
}

__global__ __launch_bounds__(256)
void ktv_reduce(const float* __restrict__ Mpart, float* __restrict__ Mout)
{
    const int idx = blockIdx.x * 256 + threadIdx.x;
    float s = 0.f;
    #pragma unroll
    for (int c = 0; c < NCH; c++)
        s += Mpart[(long)c * (Bsz * Hsz * DKsz * DKsz) + idx];
    Mout[idx] = s * 0.125f;
}

// ---------------------------------------------------------------------------
// WcombT[b][c][h*64+i] = sum_j M[b,h][i][j] * Wo[c][h*64+j]  (emit bf16 h/l)
// ---------------------------------------------------------------------------
__global__ __launch_bounds__(256)
void wcomb_kernel(const float* __restrict__ Mh, const float* __restrict__ Wo,
                  __nv_bfloat16* __restrict__ WTh, __nv_bfloat16* __restrict__ WTl)
{
    __shared__ float MshT[64 * 64];   // [j][i]
    __shared__ float WoSh[32][64];
    const int c0 = blockIdx.x * 32;
    const int h  = blockIdx.y;
    const int b  = blockIdx.z;
    const int tid = threadIdx.x;

    const float* Mp = Mh + (size_t)(b * Hsz + h) * (DKsz * DKsz);
    #pragma unroll
    for (int t = tid; t < 4096; t += 256) {
        const int i = t >> 6, j = t & 63;
        MshT[j * 64 + i] = Mp[t];
    }
    #pragma unroll
    for (int t = tid; t < 2048; t += 256) {
        const int cc = t >> 6, j = t & 63;
        WoSh[cc][j] = Wo[(size_t)(c0 + cc) * Dsz + h * DKsz + j];
    }
    __syncthreads();

    const int cc = tid >> 3;
    const int i0 = (tid & 7) * 8;
    float acc[8] = {};
    #pragma unroll
    for (int j = 0; j < 64; j++) {
        const float w = WoSh[cc][j];
        #pragma unroll
        for (int u = 0; u < 8; u++) acc[u] += w * MshT[j * 64 + i0 + u];
    }
    const long off = (long)(b * Dsz + c0 + cc) * Dsz + h * DKsz + i0;
    #pragma unroll
    for (int u = 0; u < 8; u += 2) {
        __nv_bfloat16 h0 = __float2bfloat16_rn(acc[u]);
        __nv_bfloat16 h1 = __float2bfloat16_rn(acc[u + 1]);
        *(__nv_bfloat162*)(WTh + off + u) = __halves2bfloat162(h0, h1);
        *(__nv_bfloat162*)(WTl + off + u) = __halves2bfloat162(
            __float2bfloat16_rn(acc[u] - __bfloat162float(h0)),
            __float2bfloat16_rn(acc[u + 1] - __bfloat162float(h1)));
    }
}

// ---------------------------------------------------------------------------
extern "C" void kernel_launch(void* const* d_in, const int* in_sizes, int n_in,
                              void* d_out, int out_size)
{
    const float* q  = (const float*)d_in[0];
    const float* k  = (const float*)d_in[1];
    const float* v  = (const float*)d_in[2];
    const float* wq = (const float*)d_in[3];
    const float* bq = (const float*)d_in[4];
    const float* wk = (const float*)d_in[5];
    const float* bk = (const float*)d_in[6];
    const float* wv = (const float*)d_in[7];
    const float* bv = (const float*)d_in[8];
    const float* wo = (const float*)d_in[9];
    const float* bo = (const float*)d_in[10];
    float* out = (float*)d_out;

    __nv_bfloat16 *qh, *ql, *kh, *kl, *vh, *vl;
    __nv_bfloat16 *wqh, *wql, *wkh, *wkl, *wvh, *wvl;
    __nv_bfloat16 *Qh, *Ql, *WTh, *WTl;
    float *K, *V, *Mp, *Mb;
    cudaGetSymbolAddress((void**)&qh, g_qh);   cudaGetSymbolAddress((void**)&ql, g_ql);
    cudaGetSymbolAddress((void**)&kh, g_kh);   cudaGetSymbolAddress((void**)&kl, g_kl);
    cudaGetSymbolAddress((void**)&vh, g_vh);   cudaGetSymbolAddress((void**)&vl, g_vl);
    cudaGetSymbolAddress((void**)&wqh, g_wqh); cudaGetSymbolAddress((void**)&wql, g_wql);
    cudaGetSymbolAddress((void**)&wkh, g_wkh); cudaGetSymbolAddress((void**)&wkl, g_wkl);
    cudaGetSymbolAddress((void**)&wvh, g_wvh); cudaGetSymbolAddress((void**)&wvl, g_wvl);
    cudaGetSymbolAddress((void**)&Qh, g_Qh);   cudaGetSymbolAddress((void**)&Ql, g_Ql);
    cudaGetSymbolAddress((void**)&K, g_K);     cudaGetSymbolAddress((void**)&V, g_V);
    cudaGetSymbolAddress((void**)&Mp, g_Mpart);
    cudaGetSymbolAddress((void**)&Mb, g_M);
    cudaGetSymbolAddress((void**)&WTh, g_WTh); cudaGetSymbolAddress((void**)&WTl, g_WTl);

    static int smem_set = 0;
    if (!smem_set) {
        cudaFuncSetAttribute(gemm_bf16, cudaFuncAttributeMaxDynamicSharedMemorySize,
                             2 * STAGE_H * 2);
        smem_set = 1;
    }
    const int gsmem = 2 * STAGE_H * 2;  // bytes (2 stages x STAGE_H halves)

    // 0) splits
    split_kernel<<<NELEM / 4 / 256, 256>>>(q, qh, ql, NELEM / 4);
    split_kernel<<<NELEM / 4 / 256, 256>>>(k, kh, kl, NELEM / 4);
    split_kernel<<<NELEM / 4 / 256, 256>>>(v, vh, vl, NELEM / 4);
    split_kernel<<<WELEM / 4 / 256, 256>>>(wq, wqh, wql, WELEM / 4);
    split_kernel<<<WELEM / 4 / 256, 256>>>(wk, wkh, wkl, WELEM / 4);
    split_kernel<<<WELEM / 4 / 256, 256>>>(wv, wvh, wvl, WELEM / 4);

    // 1) projections
    const dim3 gp(Dsz / 128, (Bsz * Ssz) / 128, 1);   // (8, 32)
    gemm_bf16<<<gp, 256, gsmem>>>(qh, ql, wqh, wql, bq, nullptr, Qh, Ql,
                                  Bsz * Ssz, Dsz, Dsz, 0, 0, 0);
    gemm_bf16<<<gp, 256, gsmem>>>(kh, kl, wkh, wkl, bk, K, nullptr, nullptr,
                                  Bsz * Ssz, Dsz, Dsz, 0, 0, 0);
    gemm_bf16<<<gp, 256, gsmem>>>(vh, vl, wvh, wvl, bv, V, nullptr, nullptr,
                                  Bsz * Ssz, Dsz, Dsz, 0, 0, 0);

    // 2) M = K^T V / 8
    ktv_kernel<<<dim3(Bsz * Hsz, NCH), 256>>>(K, V, Mp);
    ktv_reduce<<<(Bsz * Hsz * DKsz * DKsz) / 256, 256>>>(Mp, Mb);

    // 3) fold into output weight (bf16 h/l)
    wcomb_kernel<<<dim3(Dsz / 32, Hsz, Bsz), 256>>>(Mb, wo, WTh, WTl);

    // 4) output GEMM (batched over B), fp32 out
    gemm_bf16<<<dim3(Dsz / 128, Ssz / 128, Bsz), 256, gsmem>>>(
        Qh, Ql, WTh, WTl, bo, out, nullptr, nullptr,
        Ssz, Dsz, Dsz, (long)Ssz * Dsz, (long)Dsz * Dsz, (long)Ssz * Dsz);
}

// round 5
// speedup vs baseline: 1.1176x; 1.1176x over previous
#include <cuda_runtime.h>
#include <cuda_bf16.h>
#include <cstdint>

// ---------------------------------------------------------------------------
// MultiHeadAttentionBlock — softmax result DISCARDED => attention is LINEAR:
//   (Q K^T / 8) V == Q (K^T V / 8).
// mma.sync bf16 hi/lo split (3 MMAs) — tcgen05 unavailable (PTX target sm_103).
// ---------------------------------------------------------------------------

#define Bsz 2
#define Ssz 2048
#define Dsz 1024
#define Hsz 16
#define DKsz 64
#define NCH 32

#define NELEM (Bsz * Ssz * Dsz)
#define WELEM (Dsz * Dsz)

__device__ __nv_bfloat16 g_qh[NELEM], g_ql[NELEM];
__device__ __nv_bfloat16 g_kh[NELEM], g_kl[NELEM];
__device__ __nv_bfloat16 g_vh[NELEM], g_vl[NELEM];
__device__ __nv_bfloat16 g_wqh[WELEM], g_wql[WELEM];
__device__ __nv_bfloat16 g_wkh[WELEM], g_wkl[WELEM];
__device__ __nv_bfloat16 g_wvh[WELEM], g_wvl[WELEM];
__device__ __nv_bfloat16 g_Qh[NELEM], g_Ql[NELEM];
__device__ float g_K[NELEM];
__device__ float g_V[NELEM];
__device__ float g_Mpart[NCH * Bsz * Hsz * DKsz * DKsz];
__device__ float g_M[Bsz * Hsz * DKsz * DKsz];
__device__ __nv_bfloat16 g_WTh[Bsz * Dsz * Dsz], g_WTl[Bsz * Dsz * Dsz];

__device__ __forceinline__ void ldsm4(unsigned r[4], const __nv_bfloat16* p) {
    unsigned a = (unsigned)__cvta_generic_to_shared(p);
    asm volatile("ldmatrix.sync.aligned.m8n8.x4.shared.b16 {%0,%1,%2,%3}, [%4];\n"
                 : "=r"(r[0]), "=r"(r[1]), "=r"(r[2]), "=r"(r[3]) : "r"(a));
}

__device__ __forceinline__ void mma_bf16(float c[4], const unsigned a[4], const unsigned b[2]) {
    asm volatile("mma.sync.aligned.m16n8k16.row.col.f32.bf16.bf16.f32 "
                 "{%0,%1,%2,%3}, {%4,%5,%6,%7}, {%8,%9}, {%0,%1,%2,%3};\n"
                 : "+f"(c[0]), "+f"(c[1]), "+f"(c[2]), "+f"(c[3])
                 : "r"(a[0]), "r"(a[1]), "r"(a[2]), "r"(a[3]), "r"(b[0]), "r"(b[1]));
}

__device__ __forceinline__ void cpa16(void* dst, const void* src) {
    unsigned d = (unsigned)__cvta_generic_to_shared(dst);
    asm volatile("cp.async.cg.shared.global [%0], [%1], 16;\n" :: "r"(d), "l"(src));
}
__device__ __forceinline__ void cpa_commit() { asm volatile("cp.async.commit_group;\n"); }
__device__ __forceinline__ void cpa_wait1()  { asm volatile("cp.async.wait_group 1;\n"); }
__device__ __forceinline__ void cpa_wait0()  { asm volatile("cp.async.wait_group 0;\n"); }

__global__ __launch_bounds__(256)
void split_kernel(const float* __restrict__ x, __nv_bfloat16* __restrict__ xh,
                  __nv_bfloat16* __restrict__ xl, int n4)
{
    const int i = blockIdx.x * 256 + threadIdx.x;
    if (i >= n4) return;
    float4 v = ((const float4*)x)[i];
    __nv_bfloat16 h0 = __float2bfloat16_rn(v.x), h1 = __float2bfloat16_rn(v.y);
    __nv_bfloat16 h2 = __float2bfloat16_rn(v.z), h3 = __float2bfloat16_rn(v.w);
    ((__nv_bfloat162*)xh)[2 * i]     = __halves2bfloat162(h0, h1);
    ((__nv_bfloat162*)xh)[2 * i + 1] = __halves2bfloat162(h2, h3);
    ((__nv_bfloat162*)xl)[2 * i]     = __halves2bfloat162(
        __float2bfloat16_rn(v.x - __bfloat162float(h0)),
        __float2bfloat16_rn(v.y - __bfloat162float(h1)));
    ((__nv_bfloat162*)xl)[2 * i + 1] = __halves2bfloat162(
        __float2bfloat16_rn(v.z - __bfloat162float(h2)),
        __float2bfloat16_rn(v.w - __bfloat162float(h3)));
}

#define PITCH 40
#define ARR_H (128 * PITCH)
#define STAGE_H (4 * ARR_H)
#define GSMEM (2 * STAGE_H * 2)

__global__ __launch_bounds__(128)
void gemm_mma(const __nv_bfloat16* __restrict__ Agh, const __nv_bfloat16* __restrict__ Agl,
              const __nv_bfloat16* __restrict__ Bgh, const __nv_bfloat16* __restrict__ Bgl,
              const float* __restrict__ bias,
              float* __restrict__ Cf, __nv_bfloat16* __restrict__ Ch, __nv_bfloat16* __restrict__ Cl,
              int N, long sA, long sB, long sC)
{
    extern __shared__ __align__(16) __nv_bfloat16 smem[];
    const int K = Dsz;

    Agh += (long)blockIdx.z * sA; Agl += (long)blockIdx.z * sA;
    Bgh += (long)blockIdx.z * sB; Bgl += (long)blockIdx.z * sB;
    const int bm = blockIdx.y * 128, bn = blockIdx.x * 128;
    const int tid = threadIdx.x, lane = tid & 31, warp = tid >> 5;
    const int wm = warp >> 1, wn = warp & 1;

    float acc[4][8][4];
    #pragma unroll
    for (int mt = 0; mt < 4; mt++)
        #pragma unroll
        for (int nt = 0; nt < 8; nt++)
            #pragma unroll
            for (int e = 0; e < 4; e++) acc[mt][nt][e] = 0.f;

    auto load_stage = [&](int buf, int k0) {
        __nv_bfloat16* S = smem + buf * STAGE_H;
        #pragma unroll
        for (int it = 0; it < 4; it++) {
            const int idx = tid + it * 128;
            const int r = idx >> 2, c = (idx & 3) * 8;
            const long ga = (long)(bm + r) * K + k0 + c;
            const long gb = (long)(bn + r) * K + k0 + c;
            __nv_bfloat16* row = S + r * PITCH + c;
            cpa16(row,             Agh + ga);
            cpa16(row + ARR_H,     Agl + ga);
            cpa16(row + 2 * ARR_H, Bgh + gb);
            cpa16(row + 3 * ARR_H, Bgl + gb);
        }
        cpa_commit();
    };

    load_stage(0, 0);
    load_stage(1, 32);

    const int NS = K / 32;
    for (int i = 0; i < NS; i++) {
        if (i == NS - 1) cpa_wait0(); else cpa_wait1();
        __syncthreads();

        const __nv_bfloat16* S = smem + (i & 1) * STAGE_H;
        const __nv_bfloat16* sAh = S;
        const __nv_bfloat16* sAl = S + ARR_H;
        const __nv_bfloat16* sBh = S + 2 * ARR_H;
        const __nv_bfloat16* sBl = S + 3 * ARR_H;

        #pragma unroll
        for (int kk = 0; kk < 32; kk += 16) {
            unsigned aH[4][4], aL[4][4];
            const int arow = wm * 64 + (lane & 15);
            const int acol = kk + (lane >> 4) * 8;
            #pragma unroll
            for (int mt = 0; mt < 4; mt++) {
                ldsm4(aH[mt], sAh + (arow + mt * 16) * PITCH + acol);
                ldsm4(aL[mt], sAl + (arow + mt * 16) * PITCH + acol);
            }
            const int g = lane >> 3;
            #pragma unroll
            for (int half = 0; half < 2; half++) {
                unsigned bH[4][2], bL[4][2];
                #pragma unroll
                for (int p = 0; p < 2; p++) {
                    const int brow = wn * 64 + half * 32 + p * 16 + ((g >> 1) << 3) + (lane & 7);
                    const int bcol = kk + (g & 1) * 8;
                    unsigned t[4];
                    ldsm4(t, sBh + brow * PITCH + bcol);
                    bH[2 * p][0] = t[0]; bH[2 * p][1] = t[1];
                    bH[2 * p + 1][0] = t[2]; bH[2 * p + 1][1] = t[3];
                    ldsm4(t, sBl + brow * PITCH + bcol);
                    bL[2 * p][0] = t[0]; bL[2 * p][1] = t[1];
                    bL[2 * p + 1][0] = t[2]; bL[2 * p + 1][1] = t[3];
                }
                #pragma unroll
                for (int mt = 0; mt < 4; mt++)
                    #pragma unroll
                    for (int nn = 0; nn < 4; nn++) {
                        const int nt = half * 4 + nn;
                        mma_bf16(acc[mt][nt], aH[mt], bH[nn]);
                        mma_bf16(acc[mt][nt], aH[mt], bL[nn]);
                        mma_bf16(acc[mt][nt], aL[mt], bH[nn]);
                    }
            }
        }
        __syncthreads();
        if (i + 2 < NS) load_stage(i & 1, (i + 2) * 32);
    }

    const int crow = bm + wm * 64 + lane / 4;
    const int ccol0 = bn + wn * 64 + (lane % 4) * 2;
    #pragma unroll
    for (int mt = 0; mt < 4; mt++) {
        #pragma unroll
        for (int nt = 0; nt < 8; nt++) {
            const int col = ccol0 + nt * 8;
            const float2 bb = *(const float2*)(bias + col);
            const int r0 = crow + mt * 16;
            const float o00 = acc[mt][nt][0] + bb.x, o01 = acc[mt][nt][1] + bb.y;
            const float o10 = acc[mt][nt][2] + bb.x, o11 = acc[mt][nt][3] + bb.y;
            if (Cf) {
                float* Cz = Cf + (long)blockIdx.z * sC;
                *(float2*)(Cz + (long)r0 * N + col) = make_float2(o00, o01);
                *(float2*)(Cz + (long)(r0 + 8) * N + col) = make_float2(o10, o11);
            } else {
                __nv_bfloat16* Chz = Ch + (long)blockIdx.z * sC;
                __nv_bfloat16* Clz = Cl + (long)blockIdx.z * sC;
                __nv_bfloat16 h00 = __float2bfloat16_rn(o00), h01 = __float2bfloat16_rn(o01);
                __nv_bfloat16 h10 = __float2bfloat16_rn(o10), h11 = __float2bfloat16_rn(o11);
                *(__nv_bfloat162*)(Chz + (long)r0 * N + col) = __halves2bfloat162(h00, h01);
                *(__nv_bfloat162*)(Chz + (long)(r0 + 8) * N + col) = __halves2bfloat162(h10, h11);
                *(__nv_bfloat162*)(Clz + (long)r0 * N + col) = __halves2bfloat162(
                    __float2bfloat16_rn(o00 - __bfloat162float(h00)),
                    __float2bfloat16_rn(o01 - __bfloat162float(h01)));
                *(__nv_bfloat162*)(Clz + (long)(r0 + 8) * N + col) = __halves2bfloat162(
                    __float2bfloat16_rn(o10 - __bfloat162float(h10)),
                    __float2bfloat16_rn(o11 - __bfloat162float(h11)));
            }
        }
    }
}

__global__ __launch_bounds__(256)
void ktv_kernel(const float* __restrict__ Kp, const float* __restrict__ Vp,
                float* __restrict__ Mpart)
{
    __shared__ float Ks[32][64];
    __shared__ float Vs[32][64];
    const int bh = blockIdx.x;
    const int b = bh >> 4, h = bh & 15;
    const int chunk = blockIdx.y;
    const int tid = threadIdx.x;
    const int ti = (tid >> 4) * 4, tj = (tid & 15) * 4;
    const size_t base = (size_t)b * Ssz * Dsz + h * DKsz;

    float acc[4][4] = {};
    const int s_begin = chunk * (Ssz / NCH);
    for (int s0 = s_begin; s0 < s_begin + Ssz / NCH; s0 += 32) {
        #pragma unroll
        for (int it = 0; it < 2; it++) {
            const int idx = tid + it * 256;
            const int srow = idx >> 4, scol = (idx & 15) << 2;
            *(float4*)&Ks[srow][scol] = *(const float4*)(Kp + base + (size_t)(s0 + srow) * Dsz + scol);
            *(float4*)&Vs[srow][scol] = *(const float4*)(Vp + base + (size_t)(s0 + srow) * Dsz + scol);
        }
        __syncthreads();
        #pragma unroll
        for (int ss = 0; ss < 32; ss++) {
            float4 ka = *(const float4*)&Ks[ss][ti];
            float4 vb = *(const float4*)&Vs[ss][tj];
            const float a[4] = {ka.x, ka.y, ka.z, ka.w};
            const float w[4] = {vb.x, vb.y, vb.z, vb.w};
            #pragma unroll
            for (int i = 0; i < 4; i++)
                #pragma unroll
                for (int j = 0; j < 4; j++) acc[i][j] += a[i] * w[j];
        }
        __syncthreads();
    }
    float* outp = Mpart + (long)chunk * (Bsz * Hsz * DKsz * DKsz) + (long)bh * (DKsz * DKsz);
    #pragma unroll
    for (int i = 0; i < 4; i++)
        *(float4*)(outp + (ti + i) * DKsz + tj) = make_float4(acc[i][0], acc[i][1], acc[i][2], acc[i][3]);
}

__global__ __launch_bounds__(256)
void ktv_reduce(const float* __restrict__ Mpart, float* __restrict__ Mout)
{
    const int idx = blockIdx.x * 256 + threadIdx.x;
    float s = 0.f;
    #pragma unroll
    for (int c = 0; c < NCH; c++)
        s += Mpart[(long)c * (Bsz * Hsz * DKsz * DKsz) + idx];
    Mout[idx] = s * 0.125f;
}

__global__ __launch_bounds__(256)
void wcomb_kernel(const float* __restrict__ Mh, const float* __restrict__ Wo,
                  __nv_bfloat16* __restrict__ WTh, __nv_bfloat16* __restrict__ WTl)
{
    __shared__ float MshT[64 * 64];
    __shared__ float WoSh[32][64];
    const int c0 = blockIdx.x * 32;
    const int h = blockIdx.y, b = blockIdx.z;
    const int tid = threadIdx.x;

    const float* Mp = Mh + (size_t)(b * Hsz + h) * (DKsz * DKsz);
    #pragma unroll
    for (int t = tid; t < 4096; t += 256) {
        const int i = t >> 6, j = t & 63;
        MshT[j * 64 + i] = Mp[t];
    }
    #pragma unroll
    for (int t = tid; t < 2048; t += 256) {
        const int cc = t >> 6, j = t & 63;
        WoSh[cc][j] = Wo[(size_t)(c0 + cc) * Dsz + h * DKsz + j];
    }
    __syncthreads();

    const int cc = tid >> 3;
    const int i0 = (tid & 7) * 8;
    float acc[8] = {};
    #pragma unroll
    for (int j = 0; j < 64; j++) {
        const float w = WoSh[cc][j];
        #pragma unroll
        for (int u = 0; u < 8; u++) acc[u] += w * MshT[j * 64 + i0 + u];
    }
    const long off = (long)(b * Dsz + c0 + cc) * Dsz + h * DKsz + i0;
    #pragma unroll
    for (int u = 0; u < 8; u += 2) {
        __nv_bfloat16 h0 = __float2bfloat16_rn(acc[u]);
        __nv_bfloat16 h1 = __float2bfloat16_rn(acc[u + 1]);
        *(__nv_bfloat162*)(WTh + off + u) = __halves2bfloat162(h0, h1);
        *(__nv_bfloat162*)(WTl + off + u) = __halves2bfloat162(
            __float2bfloat16_rn(acc[u] - __bfloat162float(h0)),
            __float2bfloat16_rn(acc[u + 1] - __bfloat162float(h1)));
    }
}

extern "C" void kernel_launch(void* const* d_in, const int* in_sizes, int n_in,
                              void* d_out, int out_size)
{
    const float* q  = (const float*)d_in[0];
    const float* k  = (const float*)d_in[1];
    const float* v  = (const float*)d_in[2];
    const float* wq = (const float*)d_in[3];
    const float* bq = (const float*)d_in[4];
    const float* wk = (const float*)d_in[5];
    const float* bk = (const float*)d_in[6];
    const float* wv = (const float*)d_in[7];
    const float* bv = (const float*)d_in[8];
    const float* wo = (const float*)d_in[9];
    const float* bo = (const float*)d_in[10];
    float* out = (float*)d_out;

    __nv_bfloat16 *qh, *ql, *kh, *kl, *vh, *vl;
    __nv_bfloat16 *wqh, *wql, *wkh, *wkl, *wvh, *wvl;
    __nv_bfloat16 *Qh, *Ql, *WTh, *WTl;
    float *K, *V, *Mp, *Mb;
    cudaGetSymbolAddress((void**)&qh, g_qh);   cudaGetSymbolAddress((void**)&ql, g_ql);
    cudaGetSymbolAddress((void**)&kh, g_kh);   cudaGetSymbolAddress((void**)&kl, g_kl);
    cudaGetSymbolAddress((void**)&vh, g_vh);   cudaGetSymbolAddress((void**)&vl, g_vl);
    cudaGetSymbolAddress((void**)&wqh, g_wqh); cudaGetSymbolAddress((void**)&wql, g_wql);
    cudaGetSymbolAddress((void**)&wkh, g_wkh); cudaGetSymbolAddress((void**)&wkl, g_wkl);
    cudaGetSymbolAddress((void**)&wvh, g_wvh); cudaGetSymbolAddress((void**)&wvl, g_wvl);
    cudaGetSymbolAddress((void**)&Qh, g_Qh);   cudaGetSymbolAddress((void**)&Ql, g_Ql);
    cudaGetSymbolAddress((void**)&K, g_K);     cudaGetSymbolAddress((void**)&V, g_V);
    cudaGetSymbolAddress((void**)&Mp, g_Mpart);
    cudaGetSymbolAddress((void**)&Mb, g_M);
    cudaGetSymbolAddress((void**)&WTh, g_WTh); cudaGetSymbolAddress((void**)&WTl, g_WTl);

    static int smem_set = 0;
    if (!smem_set) {
        cudaFuncSetAttribute(gemm_mma, cudaFuncAttributeMaxDynamicSharedMemorySize, GSMEM);
        smem_set = 1;
    }

    split_kernel<<<NELEM / 4 / 256, 256>>>(q, qh, ql, NELEM / 4);
    split_kernel<<<NELEM / 4 / 256, 256>>>(k, kh, kl, NELEM / 4);
    split_kernel<<<NELEM / 4 / 256, 256>>>(v, vh, vl, NELEM / 4);
    split_kernel<<<WELEM / 4 / 256, 256>>>(wq, wqh, wql, WELEM / 4);
    split_kernel<<<WELEM / 4 / 256, 256>>>(wk, wkh, wkl, WELEM / 4);
    split_kernel<<<WELEM / 4 / 256, 256>>>(wv, wvh, wvl, WELEM / 4);

    const dim3 gp(Dsz / 128, (Bsz * Ssz) / 128, 1);
    gemm_mma<<<gp, 128, GSMEM>>>(qh, ql, wqh, wql, bq, nullptr, Qh, Ql, Dsz, 0, 0, 0);
    gemm_mma<<<gp, 128, GSMEM>>>(kh, kl, wkh, wkl, bk, K, nullptr, nullptr, Dsz, 0, 0, 0);
    gemm_mma<<<gp, 128, GSMEM>>>(vh, vl, wvh, wvl, bv, V, nullptr, nullptr, Dsz, 0, 0, 0);

    ktv_kernel<<<dim3(Bsz * Hsz, NCH), 256>>>(K, V, Mp);
    ktv_reduce<<<(Bsz * Hsz * DKsz * DKsz) / 256, 256>>>(Mp, Mb);

    wcomb_kernel<<<dim3(Dsz / 32, Hsz, Bsz), 256>>>(Mb, wo, WTh, WTl);

    gemm_mma<<<dim3(Dsz / 128, Ssz / 128, Bsz), 128, GSMEM>>>(
        Qh, Ql, WTh, WTl, bo, out, nullptr, nullptr,
        Dsz, (long)Ssz * Dsz, (long)Dsz * Dsz, (long)Ssz * Dsz);
}